// round 4
// baseline (speedup 1.0000x reference)
#include <cuda_runtime.h>
#include <math.h>

#define NB 16
#define NI 1024
#define NO 64
#define CH 64
#define EPSV 1e-5f

// Scratch (static __device__ globals — the sanctioned allocation-free scratch)
__device__ float g_V[(size_t)NB * NI * NO * CH];   // 256 MB vote tensor [b][i][j*64+c*16+h]
__device__ float g_S1[NB * NO * CH];
__device__ float g_S2[NB * NO * CH];
__device__ float g_S0[NB * NO];
__device__ float g_aout[NB * NO];
__device__ float g_A[NB * NO * CH];   // 1/(2 sig2)
__device__ float g_G[NB * NO * CH];   // mu/sig2
__device__ float g_c0[NB * NO];
__device__ float g_la[NB * NO];       // log_sigmoid(a_out)

__global__ void k_zero() {
    int idx = blockIdx.x * 256 + threadIdx.x;
    if (idx < NB * NO * CH) { g_S1[idx] = 0.f; g_S2[idx] = 0.f; }
    if (idx < NB * NO)      { g_S0[idx] = 0.f; g_aout[idx] = 0.f; }
}

// V[b,i,j,c,h] = sum_d mu[b,i,c,d] * W[i,j,d,h] + B[i,j,c,h]
// One block per i. mu-slice (64x16) and B-slice (4096) in smem, W held in
// registers. Thread t owns (j = t>>2, h = (t&3)*4 .. +3) for all 64 m=(b,c):
// one float4 store per m -> fully coalesced 128B transactions on the V write.
__global__ __launch_bounds__(256) void k_computeV(const float* __restrict__ mu,
                                                  const float* __restrict__ W,
                                                  const float* __restrict__ Bp) {
    int i = blockIdx.x;
    int t = threadIdx.x;
    __shared__ float As[64][16];     // [m=(b*4+c)][d]
    __shared__ float Bs[4096];       // [j*64 + c*16 + h]

    for (int e = t; e < 1024; e += 256) {
        int m = e >> 4, d = e & 15;
        int b = m >> 2, c = m & 3;
        As[m][d] = mu[((size_t)b * NI + i) * 64 + c * 16 + d];
    }
    {
        const float4* Bp4 = (const float4*)(Bp + (size_t)i * 4096);
        float4* Bs4 = (float4*)Bs;
        for (int e = t; e < 1024; e += 256) Bs4[e] = Bp4[e];
    }
    __syncthreads();

    const float* Wi = W + (size_t)i * 16384;
    int j = t >> 2;
    int q = t & 3;

    float w[4][16];                  // w[hh][d] for h = q*4+hh
    #pragma unroll
    for (int hh = 0; hh < 4; hh++) {
        int h = q * 4 + hh;
        #pragma unroll
        for (int d = 0; d < 16; d++) w[hh][d] = Wi[j * 256 + d * 16 + h];
    }

    for (int m = 0; m < 64; m++) {
        float a[16];
        #pragma unroll
        for (int d = 0; d < 16; d++) a[d] = As[m][d];
        int b = m >> 2, c = m & 3;
        float acc[4];
        #pragma unroll
        for (int hh = 0; hh < 4; hh++) {
            float s = Bs[j * 64 + c * 16 + q * 4 + hh];
            #pragma unroll
            for (int d = 0; d < 16; d++) s = fmaf(a[d], w[hh][d], s);
            acc[hh] = s;
        }
        float4 r; r.x = acc[0]; r.y = acc[1]; r.z = acc[2]; r.w = acc[3];
        size_t off = (size_t)b * (NI * 4096ull) + (size_t)i * 4096
                   + (size_t)j * 64 + c * 16 + q * 4;
        *(float4*)(g_V + off) = r;
    }
}

// One routing iteration: block = (b, i-tile of 64). Thread t owns the 16
// contiguous floats [t*16, t*16+16) of each 4096-wide V row; the row stays in
// registers for both the log_p contraction and the moment accumulation.
// Moments live in registers across the tile; single atomic flush per block.
template<int IT>
__global__ __launch_bounds__(256) void k_iter(const float* __restrict__ a_inp,
                                              const float* __restrict__ beta_use,
                                              const float* __restrict__ beta_ign) {
    int b    = blockIdx.x >> 4;
    int tile = blockIdx.x & 15;
    int t    = threadIdx.x;
    int j4   = t >> 2;           // this thread's j
    int part = t & 3;            // which 16-ch quarter

    __shared__ float logit[64];
    __shared__ float Dsh[64];

    float S1r[16], S2r[16];
    #pragma unroll
    for (int c = 0; c < 16; c++) { S1r[c] = 0.f; S2r[c] = 0.f; }
    float s0p = 0.f, aop = 0.f;  // only meaningful for t<64

    float Aq[16], Gq[16];
    float la_c0 = 0.f;
    if (IT > 0) {
        const float4* Ap = (const float4*)(g_A + b * 4096 + t * 16);
        const float4* Gp = (const float4*)(g_G + b * 4096 + t * 16);
        #pragma unroll
        for (int qq = 0; qq < 4; qq++) {
            float4 av = Ap[qq], gv = Gp[qq];
            Aq[qq*4+0]=av.x; Aq[qq*4+1]=av.y; Aq[qq*4+2]=av.z; Aq[qq*4+3]=av.w;
            Gq[qq*4+0]=gv.x; Gq[qq*4+1]=gv.y; Gq[qq*4+2]=gv.z; Gq[qq*4+3]=gv.w;
        }
        la_c0 = g_la[b * 64 + j4] - g_c0[b * 64 + j4];
    }

    for (int il = 0; il < 64; il++) {
        int i = tile * 64 + il;
        const float4* Vp = (const float4*)(g_V + (size_t)b * (NI * 4096ull)
                                               + (size_t)i * 4096 + t * 16);
        float v[16];
        #pragma unroll
        for (int qq = 0; qq < 4; qq++) {
            float4 vv = Vp[qq];
            v[qq*4+0]=vv.x; v[qq*4+1]=vv.y; v[qq*4+2]=vv.z; v[qq*4+3]=vv.w;
        }
        float fa = 1.f / (1.f + __expf(-a_inp[b * NI + i]));

        if (IT > 0) {
            // log_p partial over this thread's 16 channels
            float s = 0.f;
            #pragma unroll
            for (int c = 0; c < 16; c++) s += v[c] * (Gq[c] - v[c] * Aq[c]);
            s += __shfl_xor_sync(0xffffffffu, s, 1);
            s += __shfl_xor_sync(0xffffffffu, s, 2);
            if (part == 0) logit[j4] = s + la_c0;
            __syncthreads();
            // softmax over 64 j's by warp 0
            if (t < 32) {
                float l0 = logit[t], l1 = logit[t + 32];
                float mx = fmaxf(l0, l1);
                #pragma unroll
                for (int o = 16; o; o >>= 1) mx = fmaxf(mx, __shfl_xor_sync(0xffffffffu, mx, o));
                float e0 = __expf(l0 - mx), e1 = __expf(l1 - mx);
                float ss = e0 + e1;
                #pragma unroll
                for (int o = 16; o; o >>= 1) ss += __shfl_xor_sync(0xffffffffu, ss, o);
                float inv = fa / ss;
                Dsh[t] = e0 * inv; Dsh[t + 32] = e1 * inv;
            }
            __syncthreads();
        } else {
            if (t < 64) Dsh[t] = fa * (1.f / 64.f);   // uniform R = 1/n_out
            __syncthreads();
        }

        float d = Dsh[j4];
        #pragma unroll
        for (int c = 0; c < 16; c++) {
            S1r[c] = fmaf(d, v[c], S1r[c]);
            S2r[c] = fmaf(d * v[c], v[c], S2r[c]);
        }
        if (t < 64) {
            float dd = Dsh[t];
            s0p += dd;
            aop += beta_use[i * 64 + t] * dd - beta_ign[i * 64 + t] * (fa - dd);
        }
        __syncthreads();   // protect Dsh/logit before next i
    }

    float* s1g = g_S1 + b * 4096 + t * 16;
    float* s2g = g_S2 + b * 4096 + t * 16;
    #pragma unroll
    for (int c = 0; c < 16; c++) { atomicAdd(s1g + c, S1r[c]); atomicAdd(s2g + c, S2r[c]); }
    if (t < 64) {
        atomicAdd(g_S0 + b * 64 + t, s0p);
        atomicAdd(g_aout + b * 64 + t, aop);
    }
}

// Per (b,j): mu, sig2 from moments; either write outputs (LAST) or the
// next-iteration coefficients A, G, c0, log_sigmoid(a_out). The non-LAST
// variant also re-zeroes the accumulators it consumed (it is the unique
// reader), so no separate zeroing launch is needed between iterations.
template<bool LAST>
__global__ void k_finalize(float* __restrict__ out) {
    int bj = blockIdx.x;     // 0..1023 = b*64+j
    int ch = threadIdx.x;    // 0..63
    float S0 = g_S0[bj];
    float over = 1.f / (S0 + EPSV);
    float s1 = g_S1[bj * 64 + ch];
    float s2 = g_S2[bj * 64 + ch];
    float m  = s1 * over;
    float sig2 = (s2 - 2.f * m * s1 + m * m * S0) * over + EPSV;

    if (LAST) {
        if (ch == 0) out[bj] = g_aout[bj];
        out[1024 + bj * 64 + ch] = m;
        out[1024 + NB * NO * CH + bj * 64 + ch] = sig2;
    } else {
        float Ac = 0.5f / sig2;
        g_A[bj * 64 + ch] = Ac;
        g_G[bj * 64 + ch] = m / sig2;
        g_S1[bj * 64 + ch] = 0.f;               // re-arm accumulators
        g_S2[bj * 64 + ch] = 0.f;
        float c = m * m * Ac + 0.5f * logf(sig2);
        #pragma unroll
        for (int o = 16; o; o >>= 1) c += __shfl_xor_sync(0xffffffffu, c, o);
        __shared__ float red[2];
        if ((ch & 31) == 0) red[ch >> 5] = c;
        __syncthreads();
        if (ch == 0) {
            g_c0[bj] = red[0] + red[1];
            float a = g_aout[bj];
            g_la[bj] = fminf(a, 0.f) - log1pf(__expf(-fabsf(a)));  // log_sigmoid
            g_S0[bj] = 0.f;
            g_aout[bj] = 0.f;
        }
    }
}

extern "C" void kernel_launch(void* const* d_in, const int* in_sizes, int n_in,
                              void* d_out, int out_size) {
    const float* a_inp = (const float*)d_in[0];
    const float* mu    = (const float*)d_in[1];
    const float* W     = (const float*)d_in[2];
    const float* Bp    = (const float*)d_in[3];
    const float* bu    = (const float*)d_in[4];
    const float* bi    = (const float*)d_in[5];
    float* out = (float*)d_out;

    const int ZG = (NB * NO * CH + 255) / 256;

    k_computeV<<<NI, 256>>>(mu, W, Bp);
    k_zero<<<ZG, 256>>>();                       // arm accumulators once

    k_iter<0><<<NB * 16, 256>>>(a_inp, bu, bi);
    k_finalize<false><<<NB * NO, 64>>>(nullptr); // stats -> coeffs, re-zero

    k_iter<1><<<NB * 16, 256>>>(a_inp, bu, bi);
    k_finalize<false><<<NB * NO, 64>>>(nullptr);

    k_iter<2><<<NB * 16, 256>>>(a_inp, bu, bi);
    k_finalize<true><<<NB * NO, 64>>>(out);
}

// round 6
// speedup vs baseline: 1.1402x; 1.1402x over previous
#include <cuda_runtime.h>
#include <math.h>

#define NB 16
#define NI 1024
#define NO 64
#define CH 64
#define EPSV 1e-5f
#define TILE 32   // i's per k_iter block -> NB*32 = 512 blocks

typedef unsigned long long ull;

// ---------------- scratch (static __device__ globals) ----------------
__device__ float g_V[(size_t)NB * NI * NO * CH];   // 256 MB  [b][i][j*64+c*16+h]
__device__ float g_S1b[3][NB * NO * CH];           // moment banks per iteration
__device__ float g_S2b[3][NB * NO * CH];
__device__ float g_S0b[3][NB * NO];
__device__ float g_aoutb[3][NB * NO];

// ---------------- f32x2 helpers ----------------
__device__ __forceinline__ ull pack2(float lo, float hi) {
    ull r; asm("mov.b64 %0, {%1, %2};" : "=l"(r) : "f"(lo), "f"(hi)); return r;
}
__device__ __forceinline__ void unpack2(ull v, float& lo, float& hi) {
    asm("mov.b64 {%0, %1}, %2;" : "=f"(lo), "=f"(hi) : "l"(v));
}
__device__ __forceinline__ void fma2(ull& d, ull a, ull b) {
    asm("fma.rn.f32x2 %0, %1, %2, %0;" : "+l"(d) : "l"(a), "l"(b));
}

// ---------------- zero all banks once ----------------
__global__ void k_zero() {
    int idx = blockIdx.x * 256 + threadIdx.x;        // grid covers 3*65536
    if (idx < 3 * NB * NO * CH) {
        ((float*)g_S1b)[idx] = 0.f;
        ((float*)g_S2b)[idx] = 0.f;
    }
    if (idx < 3 * NB * NO) {
        ((float*)g_S0b)[idx] = 0.f;
        ((float*)g_aoutb)[idx] = 0.f;
    }
}

// ---------------- V generation ----------------
// V[b,i,j,c,h] = sum_d mu[b,i,c,d]*W[i,j,d,h] + B[i,j,c,h].  One block per i.
// mu held in smem as broadcast-duplicated f32 pairs; W,B packed in registers.
// Inner product runs on paired fma.rn.f32x2 (half the FMA-pipe instructions).
__global__ __launch_bounds__(256) void k_computeV(const float* __restrict__ mu,
                                                  const float* __restrict__ W,
                                                  const float* __restrict__ Bp) {
    int i = blockIdx.x;
    int t = threadIdx.x;
    __shared__ ull As2[64][16];    // [m=(b*4+c)][d], both halves = mu value

    for (int e = t; e < 1024; e += 256) {
        int m = e >> 4, d = e & 15;
        int b = m >> 2, c = m & 3;
        float val = mu[((size_t)b * NI + i) * 64 + c * 16 + d];
        As2[m][d] = pack2(val, val);
    }
    __syncthreads();

    int j = t >> 2;                // thread owns (j, h = q*4..q*4+3)
    int q = t & 3;

    ull w01[16], w23[16];
    const float* Wi = W + (size_t)i * 16384;
    #pragma unroll
    for (int d = 0; d < 16; d++) {
        float4 w4 = *(const float4*)(Wi + j * 256 + d * 16 + q * 4);
        w01[d] = pack2(w4.x, w4.y);
        w23[d] = pack2(w4.z, w4.w);
    }
    ull b01[4], b23[4];
    const float* Bi = Bp + (size_t)i * 4096;
    #pragma unroll
    for (int c = 0; c < 4; c++) {
        float4 b4 = *(const float4*)(Bi + j * 64 + c * 16 + q * 4);
        b01[c] = pack2(b4.x, b4.y);
        b23[c] = pack2(b4.z, b4.w);
    }

    #pragma unroll 4
    for (int m = 0; m < 64; m++) {
        int bb = m >> 2, c = m & 3;
        ull a0 = b01[c], a1 = b23[c];
        #pragma unroll
        for (int d = 0; d < 16; d++) {
            ull aa = As2[m][d];
            fma2(a0, aa, w01[d]);
            fma2(a1, aa, w23[d]);
        }
        float4 r;
        unpack2(a0, r.x, r.y);
        unpack2(a1, r.z, r.w);
        size_t off = (size_t)bb * (NI * 4096ull) + (size_t)i * 4096
                   + (size_t)j * 64 + c * 16 + q * 4;
        *(float4*)(g_V + off) = r;
    }
}

__device__ __forceinline__ void load_row(float v[16], const float* p) {
    const float4* p4 = (const float4*)p;
    #pragma unroll
    for (int qq = 0; qq < 4; qq++) {
        float4 vv = p4[qq];
        v[qq*4+0]=vv.x; v[qq*4+1]=vv.y; v[qq*4+2]=vv.z; v[qq*4+3]=vv.w;
    }
}
__device__ __forceinline__ float sigmoidf_(float x) {
    return 1.f / (1.f + __expf(-x));
}

// ---------------- iteration 0: uniform R -> pure streaming ----------------
__global__ __launch_bounds__(256) void k_iter0(const float* __restrict__ a_inp,
                                               const float* __restrict__ beta_use,
                                               const float* __restrict__ beta_ign) {
    int b    = blockIdx.x >> 5;
    int tile = blockIdx.x & 31;
    int t    = threadIdx.x;

    float S1r[16], S2r[16];
    #pragma unroll
    for (int c = 0; c < 16; c++) { S1r[c] = 0.f; S2r[c] = 0.f; }
    float s0p = 0.f, aop = 0.f;

    const float* vbase = g_V + (size_t)b * (NI * 4096ull) + t * 16;
    #pragma unroll 2
    for (int il = 0; il < TILE; il++) {
        int i = tile * TILE + il;
        float v[16];
        load_row(v, vbase + (size_t)i * 4096);
        float fa = sigmoidf_(a_inp[b * NI + i]);
        float d = fa * (1.f / 64.f);
        #pragma unroll
        for (int c = 0; c < 16; c++) {
            S1r[c] = fmaf(d, v[c], S1r[c]);
            S2r[c] = fmaf(d * v[c], v[c], S2r[c]);
        }
        if (t < 64) {
            s0p += d;
            aop += beta_use[i * 64 + t] * d - beta_ign[i * 64 + t] * (fa - d);
        }
    }
    float* s1g = g_S1b[0] + b * 4096 + t * 16;
    float* s2g = g_S2b[0] + b * 4096 + t * 16;
    #pragma unroll
    for (int c = 0; c < 16; c++) { atomicAdd(s1g + c, S1r[c]); atomicAdd(s2g + c, S2r[c]); }
    if (t < 64) {
        atomicAdd(g_S0b[0] + b * 64 + t, s0p);
        atomicAdd(g_aoutb[0] + b * 64 + t, aop);
    }
}

// ---------------- iterations 1,2: softmax routing ----------------
// Reads moment bank IT-1 (computing A,G,c0,log_sigmoid inline), writes bank IT.
// V rows are software-pipelined one i ahead of the barrier/softmax sequence.
template<int IT>
__device__ __forceinline__ void process_row(
    const float v[16], float fa, int i, int t, int j4, int part,
    float* logit, float* Dsh,
    const float Aq[16], const float Gq[16], float la_c0,
    float S1r[16], float S2r[16], float& s0p, float& aop,
    const float* __restrict__ beta_use, const float* __restrict__ beta_ign)
{
    float s = 0.f;
    #pragma unroll
    for (int c = 0; c < 16; c++) s += v[c] * (Gq[c] - v[c] * Aq[c]);
    s += __shfl_xor_sync(0xffffffffu, s, 1);
    s += __shfl_xor_sync(0xffffffffu, s, 2);
    if (part == 0) logit[j4] = s + la_c0;
    __syncthreads();
    if (t < 32) {
        float l0 = logit[t], l1 = logit[t + 32];
        float mx = fmaxf(l0, l1);
        #pragma unroll
        for (int o = 16; o; o >>= 1) mx = fmaxf(mx, __shfl_xor_sync(0xffffffffu, mx, o));
        float e0 = __expf(l0 - mx), e1 = __expf(l1 - mx);
        float ss = e0 + e1;
        #pragma unroll
        for (int o = 16; o; o >>= 1) ss += __shfl_xor_sync(0xffffffffu, ss, o);
        float inv = fa / ss;
        Dsh[t] = e0 * inv; Dsh[t + 32] = e1 * inv;
    }
    __syncthreads();
    float d = Dsh[j4];
    #pragma unroll
    for (int c = 0; c < 16; c++) {
        S1r[c] = fmaf(d, v[c], S1r[c]);
        S2r[c] = fmaf(d * v[c], v[c], S2r[c]);
    }
    if (t < 64) {
        float dd = Dsh[t];
        s0p += dd;
        aop += beta_use[i * 64 + t] * dd - beta_ign[i * 64 + t] * (fa - dd);
    }
    // no trailing barrier needed: next logit write is ordered against warp0's
    // logit read by the softmax barrier above; next Dsh write is ordered
    // against this Dsh read by the next logit barrier.
}

template<int IT>
__global__ __launch_bounds__(256) void k_iter(const float* __restrict__ a_inp,
                                              const float* __restrict__ beta_use,
                                              const float* __restrict__ beta_ign) {
    int b    = blockIdx.x >> 5;
    int tile = blockIdx.x & 31;
    int t    = threadIdx.x;
    int j4   = t >> 2;
    int part = t & 3;

    __shared__ float logit[64];
    __shared__ float Dsh[64];

    // inline finalize of previous iteration's moments
    float Aq[16], Gq[16];
    float la_c0;
    {
        float S0 = g_S0b[IT-1][b * 64 + j4];
        float over = 1.f / (S0 + EPSV);
        const float4* S1p = (const float4*)(g_S1b[IT-1] + b * 4096 + t * 16);
        const float4* S2p = (const float4*)(g_S2b[IT-1] + b * 4096 + t * 16);
        float s1[16], s2[16];
        #pragma unroll
        for (int qq = 0; qq < 4; qq++) {
            float4 x = S1p[qq], y = S2p[qq];
            s1[qq*4+0]=x.x; s1[qq*4+1]=x.y; s1[qq*4+2]=x.z; s1[qq*4+3]=x.w;
            s2[qq*4+0]=y.x; s2[qq*4+1]=y.y; s2[qq*4+2]=y.z; s2[qq*4+3]=y.w;
        }
        float c0p = 0.f;
        #pragma unroll
        for (int c = 0; c < 16; c++) {
            float m = s1[c] * over;
            float sig2 = (s2[c] - 2.f * m * s1[c] + m * m * S0) * over + EPSV;
            float A = 0.5f / sig2;
            Aq[c] = A;
            Gq[c] = m / sig2;
            c0p += m * m * A + 0.5f * logf(sig2);
        }
        c0p += __shfl_xor_sync(0xffffffffu, c0p, 1);
        c0p += __shfl_xor_sync(0xffffffffu, c0p, 2);
        float a = g_aoutb[IT-1][b * 64 + j4];
        float la = fminf(a, 0.f) - log1pf(__expf(-fabsf(a)));
        la_c0 = la - c0p;
    }

    float S1r[16], S2r[16];
    #pragma unroll
    for (int c = 0; c < 16; c++) { S1r[c] = 0.f; S2r[c] = 0.f; }
    float s0p = 0.f, aop = 0.f;

    const float* vbase = g_V + (size_t)b * (NI * 4096ull) + t * 16;
    int i0 = tile * TILE;

    float va[16], vb[16], fa_a, fa_b;
    load_row(va, vbase + (size_t)i0 * 4096);
    fa_a = sigmoidf_(a_inp[b * NI + i0]);

    #pragma unroll 1
    for (int il = 0; il < TILE; il += 2) {
        int i = i0 + il;
        // prefetch i+1 while processing i
        load_row(vb, vbase + (size_t)(i + 1) * 4096);
        fa_b = sigmoidf_(a_inp[b * NI + i + 1]);
        process_row<IT>(va, fa_a, i, t, j4, part, logit, Dsh,
                        Aq, Gq, la_c0, S1r, S2r, s0p, aop, beta_use, beta_ign);
        // prefetch i+2 (clamped at tile end) while processing i+1
        int in2 = (il + 2 < TILE) ? i + 2 : i;
        load_row(va, vbase + (size_t)in2 * 4096);
        fa_a = sigmoidf_(a_inp[b * NI + in2]);
        process_row<IT>(vb, fa_b, i + 1, t, j4, part, logit, Dsh,
                        Aq, Gq, la_c0, S1r, S2r, s0p, aop, beta_use, beta_ign);
    }

    float* s1g = g_S1b[IT] + b * 4096 + t * 16;
    float* s2g = g_S2b[IT] + b * 4096 + t * 16;
    #pragma unroll
    for (int c = 0; c < 16; c++) { atomicAdd(s1g + c, S1r[c]); atomicAdd(s2g + c, S2r[c]); }
    if (t < 64) {
        atomicAdd(g_S0b[IT] + b * 64 + t, s0p);
        atomicAdd(g_aoutb[IT] + b * 64 + t, aop);
    }
}

// ---------------- final output from bank 2 ----------------
__global__ void k_final(float* __restrict__ out) {
    int bj = blockIdx.x;     // b*64+j
    int ch = threadIdx.x;    // 0..63
    float S0 = g_S0b[2][bj];
    float over = 1.f / (S0 + EPSV);
    float s1 = g_S1b[2][bj * 64 + ch];
    float s2 = g_S2b[2][bj * 64 + ch];
    float m  = s1 * over;
    float sig2 = (s2 - 2.f * m * s1 + m * m * S0) * over + EPSV;
    if (ch == 0) out[bj] = g_aoutb[2][bj];
    out[1024 + bj * 64 + ch] = m;
    out[1024 + NB * NO * CH + bj * 64 + ch] = sig2;
}

extern "C" void kernel_launch(void* const* d_in, const int* in_sizes, int n_in,
                              void* d_out, int out_size) {
    const float* a_inp = (const float*)d_in[0];
    const float* mu    = (const float*)d_in[1];
    const float* W     = (const float*)d_in[2];
    const float* Bp    = (const float*)d_in[3];
    const float* bu    = (const float*)d_in[4];
    const float* bi    = (const float*)d_in[5];
    float* out = (float*)d_out;

    k_zero<<<(3 * NB * NO * CH) / 256 + 1, 256>>>();
    k_computeV<<<NI, 256>>>(mu, W, Bp);
    k_iter0<<<NB * 32, 256>>>(a_inp, bu, bi);
    k_iter<1><<<NB * 32, 256>>>(a_inp, bu, bi);
    k_iter<2><<<NB * 32, 256>>>(a_inp, bu, bi);
    k_final<<<NB * NO, 64>>>(out);
}

// round 7
// speedup vs baseline: 1.1970x; 1.0498x over previous
#include <cuda_runtime.h>
#include <math.h>

#define NB 16
#define NI 1024
#define NO 64
#define CH 64
#define EPSV 1e-5f
#define TILE 32   // i's per k_iter block -> NB*32 = 512 blocks

typedef unsigned long long ull;

// ---------------- scratch (static __device__ globals) ----------------
__device__ float g_V[(size_t)NB * NI * NO * CH];   // 256 MB  [b][i][j*64+c*16+h]
__device__ float g_S1b[3][NB * NO * CH];           // moment banks per iteration
__device__ float g_S2b[3][NB * NO * CH];
__device__ float g_S0b[3][NB * NO];
__device__ float g_aoutb[3][NB * NO];

// ---------------- f32x2 helpers ----------------
__device__ __forceinline__ ull pack2(float lo, float hi) {
    ull r; asm("mov.b64 %0, {%1, %2};" : "=l"(r) : "f"(lo), "f"(hi)); return r;
}
__device__ __forceinline__ void unpack2(ull v, float& lo, float& hi) {
    asm("mov.b64 {%0, %1}, %2;" : "=f"(lo), "=f"(hi) : "l"(v));
}
// d = a*b + c
__device__ __forceinline__ ull fma2_3(ull a, ull b, ull c) {
    ull d; asm("fma.rn.f32x2 %0, %1, %2, %3;" : "=l"(d) : "l"(a), "l"(b), "l"(c)); return d;
}
__device__ __forceinline__ ull mul2(ull a, ull b) {
    ull d; asm("mul.rn.f32x2 %0, %1, %2;" : "=l"(d) : "l"(a), "l"(b)); return d;
}
// accumulate-in-place
__device__ __forceinline__ void fma2(ull& d, ull a, ull b) {
    asm("fma.rn.f32x2 %0, %1, %2, %0;" : "+l"(d) : "l"(a), "l"(b));
}

// ---------------- zero all banks once ----------------
__global__ void k_zero() {
    int idx = blockIdx.x * 256 + threadIdx.x;
    if (idx < 3 * NB * NO * CH) {
        ((float*)g_S1b)[idx] = 0.f;
        ((float*)g_S2b)[idx] = 0.f;
    }
    if (idx < 3 * NB * NO) {
        ((float*)g_S0b)[idx] = 0.f;
        ((float*)g_aoutb)[idx] = 0.f;
    }
}

// ---------------- V generation (unchanged from R6 passing kernel) ----------------
__global__ __launch_bounds__(256) void k_computeV(const float* __restrict__ mu,
                                                  const float* __restrict__ W,
                                                  const float* __restrict__ Bp) {
    int i = blockIdx.x;
    int t = threadIdx.x;
    __shared__ ull As2[64][16];    // [m=(b*4+c)][d], both halves = mu value

    for (int e = t; e < 1024; e += 256) {
        int m = e >> 4, d = e & 15;
        int b = m >> 2, c = m & 3;
        float val = mu[((size_t)b * NI + i) * 64 + c * 16 + d];
        As2[m][d] = pack2(val, val);
    }
    __syncthreads();

    int j = t >> 2;                // thread owns (j, h = q*4..q*4+3)
    int q = t & 3;

    ull w01[16], w23[16];
    const float* Wi = W + (size_t)i * 16384;
    #pragma unroll
    for (int d = 0; d < 16; d++) {
        float4 w4 = *(const float4*)(Wi + j * 256 + d * 16 + q * 4);
        w01[d] = pack2(w4.x, w4.y);
        w23[d] = pack2(w4.z, w4.w);
    }
    ull b01[4], b23[4];
    const float* Bi = Bp + (size_t)i * 4096;
    #pragma unroll
    for (int c = 0; c < 4; c++) {
        float4 b4 = *(const float4*)(Bi + j * 64 + c * 16 + q * 4);
        b01[c] = pack2(b4.x, b4.y);
        b23[c] = pack2(b4.z, b4.w);
    }

    #pragma unroll 4
    for (int m = 0; m < 64; m++) {
        int bb = m >> 2, c = m & 3;
        ull a0 = b01[c], a1 = b23[c];
        #pragma unroll
        for (int d = 0; d < 16; d++) {
            ull aa = As2[m][d];
            fma2(a0, aa, w01[d]);
            fma2(a1, aa, w23[d]);
        }
        float4 r;
        unpack2(a0, r.x, r.y);
        unpack2(a1, r.z, r.w);
        size_t off = (size_t)bb * (NI * 4096ull) + (size_t)i * 4096
                   + (size_t)j * 64 + c * 16 + q * 4;
        *(float4*)(g_V + off) = r;
    }
}

// ---------------- row load as 8 f32x2 pairs ----------------
__device__ __forceinline__ void load_row2(ull v[8], const float* p) {
    const ulonglong2* p2 = (const ulonglong2*)p;
    #pragma unroll
    for (int q = 0; q < 4; q++) {
        ulonglong2 x = p2[q];
        v[2*q] = x.x; v[2*q+1] = x.y;
    }
}
__device__ __forceinline__ float sigmoidf_(float x) {
    return 1.f / (1.f + __expf(-x));
}

// ---------------- iteration 0: uniform R -> pure streaming ----------------
__global__ __launch_bounds__(256) void k_iter0(const float* __restrict__ a_inp,
                                               const float* __restrict__ beta_use,
                                               const float* __restrict__ beta_ign) {
    int b    = blockIdx.x >> 5;
    int tile = blockIdx.x & 31;
    int t    = threadIdx.x;

    ull s1a[8], s2a[8];
    #pragma unroll
    for (int c = 0; c < 8; c++) { s1a[c] = pack2(0.f, 0.f); s2a[c] = s1a[c]; }
    float s0p = 0.f, aop = 0.f;

    const float* vbase = g_V + (size_t)b * (NI * 4096ull) + t * 16;
    #pragma unroll 2
    for (int il = 0; il < TILE; il++) {
        int i = tile * TILE + il;
        ull v[8];
        load_row2(v, vbase + (size_t)i * 4096);
        float fa = sigmoidf_(a_inp[b * NI + i]);
        float d = fa * (1.f / 64.f);
        ull d2 = pack2(d, d);
        #pragma unroll
        for (int c = 0; c < 8; c++) {
            fma2(s1a[c], v[c], d2);
            ull w = mul2(v[c], d2);
            fma2(s2a[c], w, v[c]);
        }
        if (t < 64) {
            s0p += d;
            aop += beta_use[i * 64 + t] * d - beta_ign[i * 64 + t] * (fa - d);
        }
    }
    float* s1g = g_S1b[0] + b * 4096 + t * 16;
    float* s2g = g_S2b[0] + b * 4096 + t * 16;
    #pragma unroll
    for (int c = 0; c < 8; c++) {
        float lo, hi;
        unpack2(s1a[c], lo, hi);
        atomicAdd(s1g + 2*c, lo); atomicAdd(s1g + 2*c + 1, hi);
        unpack2(s2a[c], lo, hi);
        atomicAdd(s2g + 2*c, lo); atomicAdd(s2g + 2*c + 1, hi);
    }
    if (t < 64) {
        atomicAdd(g_S0b[0] + b * 64 + t, s0p);
        atomicAdd(g_aoutb[0] + b * 64 + t, aop);
    }
}

// ---------------- logit partial over this thread's 16 channels ----------------
// nA2 holds NEGATED A pairs: t = v*(-A) + G ; s += v*t. Two fma2 per pair.
__device__ __forceinline__ float logit_part(const ull v[8], const ull nA2[8],
                                            const ull G2[8]) {
    ull s = pack2(0.f, 0.f);
    #pragma unroll
    for (int cp = 0; cp < 8; cp++) {
        ull tt = fma2_3(v[cp], nA2[cp], G2[cp]);
        s = fma2_3(v[cp], tt, s);
    }
    float lo, hi; unpack2(s, lo, hi);
    float r = lo + hi;
    r += __shfl_xor_sync(0xffffffffu, r, 1);
    r += __shfl_xor_sync(0xffffffffu, r, 2);
    return r;
}

// softmax over 64 logits by one warp; writes D = fa * softmax to Dsh
__device__ __forceinline__ void softmax_warp(const float* logit, float* Dsh,
                                             float fa, int lane) {
    float l0 = logit[lane], l1 = logit[lane + 32];
    float mx = fmaxf(l0, l1);
    #pragma unroll
    for (int o = 16; o; o >>= 1) mx = fmaxf(mx, __shfl_xor_sync(0xffffffffu, mx, o));
    float e0 = __expf(l0 - mx), e1 = __expf(l1 - mx);
    float ss = e0 + e1;
    #pragma unroll
    for (int o = 16; o; o >>= 1) ss += __shfl_xor_sync(0xffffffffu, ss, o);
    float inv = fa / ss;
    Dsh[lane] = e0 * inv; Dsh[lane + 32] = e1 * inv;
}

// ---------------- iterations 1,2: K=2 row batching ----------------
// Two rows per barrier pair; warp0 softmaxes row A, warp1 row B concurrently.
template<int IT>
__global__ __launch_bounds__(256) void k_iter(const float* __restrict__ a_inp,
                                              const float* __restrict__ beta_use,
                                              const float* __restrict__ beta_ign) {
    int b    = blockIdx.x >> 5;
    int tile = blockIdx.x & 31;
    int t    = threadIdx.x;
    int j4   = t >> 2;
    int part = t & 3;
    int wid  = t >> 5;
    int lane = t & 31;

    __shared__ float logitA[64], logitB[64], DshA[64], DshB[64];

    // inline finalize of previous iteration's moments -> nA2 (negated), G2, la_c0
    ull nA2[8], G2[8];
    float la_c0;
    {
        float S0 = g_S0b[IT-1][b * 64 + j4];
        float over = 1.f / (S0 + EPSV);
        const float4* S1p = (const float4*)(g_S1b[IT-1] + b * 4096 + t * 16);
        const float4* S2p = (const float4*)(g_S2b[IT-1] + b * 4096 + t * 16);
        float s1[16], s2[16];
        #pragma unroll
        for (int qq = 0; qq < 4; qq++) {
            float4 x = S1p[qq], y = S2p[qq];
            s1[qq*4+0]=x.x; s1[qq*4+1]=x.y; s1[qq*4+2]=x.z; s1[qq*4+3]=x.w;
            s2[qq*4+0]=y.x; s2[qq*4+1]=y.y; s2[qq*4+2]=y.z; s2[qq*4+3]=y.w;
        }
        float c0p = 0.f;
        float Av[16], Gv[16];
        #pragma unroll
        for (int c = 0; c < 16; c++) {
            float m = s1[c] * over;
            float sig2 = (s2[c] - 2.f * m * s1[c] + m * m * S0) * over + EPSV;
            float A = 0.5f / sig2;
            Av[c] = A;
            Gv[c] = m / sig2;
            c0p += m * m * A + 0.5f * logf(sig2);
        }
        #pragma unroll
        for (int cp = 0; cp < 8; cp++) {
            nA2[cp] = pack2(-Av[2*cp], -Av[2*cp+1]);
            G2[cp]  = pack2(Gv[2*cp], Gv[2*cp+1]);
        }
        c0p += __shfl_xor_sync(0xffffffffu, c0p, 1);
        c0p += __shfl_xor_sync(0xffffffffu, c0p, 2);
        float a = g_aoutb[IT-1][b * 64 + j4];
        float la = fminf(a, 0.f) - log1pf(__expf(-fabsf(a)));
        la_c0 = la - c0p;
    }

    ull s1a[8], s2a[8];
    #pragma unroll
    for (int c = 0; c < 8; c++) { s1a[c] = pack2(0.f, 0.f); s2a[c] = s1a[c]; }
    float s0p = 0.f, aop = 0.f;

    const float* vbase = g_V + (size_t)b * (NI * 4096ull) + t * 16;
    int ibase = tile * TILE;

    ull va[8], vb[8];
    float faA, faB;
    load_row2(va, vbase + (size_t)ibase * 4096);
    load_row2(vb, vbase + (size_t)(ibase + 1) * 4096);
    faA = sigmoidf_(a_inp[b * NI + ibase]);
    faB = sigmoidf_(a_inp[b * NI + ibase + 1]);

    #pragma unroll 1
    for (int p = 0; p < TILE / 2; p++) {
        int iA = ibase + 2 * p;
        int iB = iA + 1;
        float fcA = faA, fcB = faB;   // save before prefetch overwrites

        float lA = logit_part(va, nA2, G2);
        float lB = logit_part(vb, nA2, G2);
        if (part == 0) { logitA[j4] = lA + la_c0; logitB[j4] = lB + la_c0; }
        __syncthreads();

        if (wid == 0)      softmax_warp(logitA, DshA, fcA, lane);
        else if (wid == 1) softmax_warp(logitB, DshB, fcB, lane);
        __syncthreads();

        float dA = DshA[j4], dB = DshB[j4];

        // moments row A, then prefetch next row A (clamped on last pair)
        int nxt = (p < TILE / 2 - 1) ? iA + 2 : ibase;
        {
            ull d2 = pack2(dA, dA);
            #pragma unroll
            for (int c = 0; c < 8; c++) {
                fma2(s1a[c], va[c], d2);
                ull w = mul2(va[c], d2);
                fma2(s2a[c], w, va[c]);
            }
        }
        load_row2(va, vbase + (size_t)nxt * 4096);
        faA = sigmoidf_(a_inp[b * NI + nxt]);

        {
            ull d2 = pack2(dB, dB);
            #pragma unroll
            for (int c = 0; c < 8; c++) {
                fma2(s1a[c], vb[c], d2);
                ull w = mul2(vb[c], d2);
                fma2(s2a[c], w, vb[c]);
            }
        }
        load_row2(vb, vbase + (size_t)(nxt + 1) * 4096);
        faB = sigmoidf_(a_inp[b * NI + nxt + 1]);

        if (t < 64) {
            float duA = DshA[t], duB = DshB[t];
            s0p += duA + duB;
            aop += beta_use[iA * 64 + t] * duA - beta_ign[iA * 64 + t] * (fcA - duA)
                 + beta_use[iB * 64 + t] * duB - beta_ign[iB * 64 + t] * (fcB - duB);
        }
        // barrier at next loop-top (after logit computation) orders Dsh reads
        // here against next pair's Dsh writes; logit writes happen after the
        // second barrier of this pair, so logitA/B reuse is also safe.
    }

    float* s1g = g_S1b[IT] + b * 4096 + t * 16;
    float* s2g = g_S2b[IT] + b * 4096 + t * 16;
    #pragma unroll
    for (int c = 0; c < 8; c++) {
        float lo, hi;
        unpack2(s1a[c], lo, hi);
        atomicAdd(s1g + 2*c, lo); atomicAdd(s1g + 2*c + 1, hi);
        unpack2(s2a[c], lo, hi);
        atomicAdd(s2g + 2*c, lo); atomicAdd(s2g + 2*c + 1, hi);
    }
    if (t < 64) {
        atomicAdd(g_S0b[IT] + b * 64 + t, s0p);
        atomicAdd(g_aoutb[IT] + b * 64 + t, aop);
    }
}

// ---------------- final output from bank 2 ----------------
__global__ void k_final(float* __restrict__ out) {
    int bj = blockIdx.x;     // b*64+j
    int ch = threadIdx.x;    // 0..63
    float S0 = g_S0b[2][bj];
    float over = 1.f / (S0 + EPSV);
    float s1 = g_S1b[2][bj * 64 + ch];
    float s2 = g_S2b[2][bj * 64 + ch];
    float m  = s1 * over;
    float sig2 = (s2 - 2.f * m * s1 + m * m * S0) * over + EPSV;
    if (ch == 0) out[bj] = g_aoutb[2][bj];
    out[1024 + bj * 64 + ch] = m;
    out[1024 + NB * NO * CH + bj * 64 + ch] = sig2;
}

extern "C" void kernel_launch(void* const* d_in, const int* in_sizes, int n_in,
                              void* d_out, int out_size) {
    const float* a_inp = (const float*)d_in[0];
    const float* mu    = (const float*)d_in[1];
    const float* W     = (const float*)d_in[2];
    const float* Bp    = (const float*)d_in[3];
    const float* bu    = (const float*)d_in[4];
    const float* bi    = (const float*)d_in[5];
    float* out = (float*)d_out;

    k_zero<<<(3 * NB * NO * CH) / 256 + 1, 256>>>();
    k_computeV<<<NI, 256>>>(mu, W, Bp);
    k_iter0<<<NB * 32, 256>>>(a_inp, bu, bi);
    k_iter<1><<<NB * 32, 256>>>(a_inp, bu, bi);
    k_iter<2><<<NB * 32, 256>>>(a_inp, bu, bi);
    k_final<<<NB * NO, 64>>>(out);
}